// round 12
// baseline (speedup 1.0000x reference)
#include <cuda_runtime.h>

#define DM     64
#define NPTS   1323
#define NTHR   256
#define SPT    8                         // slots per thread
#define SPB    (NTHR * SPT)              // 2048 slots per block = 8192 points
#define NPAIR  (SPT / 2)                 // 4 pair-iterations; pair = 2 consecutive slots
#define MAXR   8                         // rows a block can span

// exact p/1323 for p < ~2^31 (magic: ceil(2^40/1323) = 831074549)
__device__ __forceinline__ unsigned rowof(unsigned p) {
    return (unsigned)(((unsigned long long)p * 831074549ull) >> 40);
}

// 256-bit global load/store (sm_100+, PTX 8.8)
__device__ __forceinline__ void ldg256cs(const float* p, float* f) {
    asm volatile("ld.global.cs.v8.f32 {%0,%1,%2,%3,%4,%5,%6,%7}, [%8];"
                 : "=f"(f[0]), "=f"(f[1]), "=f"(f[2]), "=f"(f[3]),
                   "=f"(f[4]), "=f"(f[5]), "=f"(f[6]), "=f"(f[7])
                 : "l"(p));
}
__device__ __forceinline__ void stg256cs(float* p, const float* f) {
    asm volatile("st.global.cs.v8.f32 [%0], {%1,%2,%3,%4,%5,%6,%7,%8};"
                 :: "l"(p),
                    "f"(f[0]), "f"(f[1]), "f"(f[2]), "f"(f[3]),
                    "f"(f[4]), "f"(f[5]), "f"(f[6]), "f"(f[7])
                 : "memory");
}

// one point through the inverse-Cholesky transform + gaussian
__device__ __forceinline__ float mvn_pt(float d0, float d1, float d2,
                                        float4 qa, float4 qb, float4 qc)
{
    d0 -= qa.x;
    d1 -= qa.y;
    d2 -= qa.z;
    float z0 = d0 * qa.w;
    float z1 = (d1 - qb.x * z0) * qb.y;
    float z2 = fmaf(-qb.w, z1, fmaf(-qb.z, z0, d2)) * qc.x;
    float maha = fmaf(z0, z0, fmaf(z1, z1, z2 * z2));
    return qc.y * __expf(-0.5f * maha);
}

struct SmemP { float4 qa[MAXR], qb[MAXR], qc[MAXR]; };

__global__ __launch_bounds__(NTHR) void mvn_fused_kernel(
    const float* __restrict__ rep,
    const float* __restrict__ dxyz,
    const float* __restrict__ Wm,
    const float* __restrict__ bm,
    const float* __restrict__ bs_,
    const float* __restrict__ Ws,
    float* __restrict__ out,
    int nrows)
{
    __shared__ SmemP sp;

    const int t = threadIdx.x;
    const int wid = t >> 5, lane = t & 31;

    const unsigned sBase = blockIdx.x * (unsigned)SPB;
    const unsigned r_first = rowof(4u * sBase);

    // ---- issue pair 0's loads (96B: 3 x 256-bit) before the prologue ----
    unsigned sPair = sBase + 2u * (unsigned)t;       // slots sPair, sPair+1 (consecutive)
    float f[24];
    {
        const float* dp = dxyz + (size_t)sPair * 12u;
        ldg256cs(dp + 0,  f + 0);
        ldg256cs(dp + 8,  f + 8);
        ldg256cs(dp + 16, f + 16);
    }

    // ---- prologue: warp w computes params for row r_first + w (all warps parallel) ----
    {
        int r = (int)r_first + wid;
        if (r > nrows - 1) r = nrows - 1;
        const float2 v = ((const float2*)(rep + (size_t)r * DM))[lane];

        float dots[9];
        #pragma unroll
        for (int cc = 0; cc < 9; cc++) {
            const float* w = (cc < 3) ? (Wm + cc * DM) : (Ws + (cc - 3) * DM);
            const float2 wv = ((const float2*)w)[lane];
            float partial = fmaf(v.x, wv.x, v.y * wv.y);
            #pragma unroll
            for (int off = 16; off > 0; off >>= 1)
                partial += __shfl_xor_sync(0xFFFFFFFFu, partial, off);
            dots[cc] = partial;   // full sum on every lane
        }

        float sig = 0.0f, splus = 0.0f;
        if (lane < 6) {
            sig = 1.0f / (1.0f + __expf(-(dots[3 + lane] + bs_[lane])));
            splus = __logf(1.0f + __expf(sig));   // sig in (0,1): always safe
        }
        const float L00 = __shfl_sync(0xFFFFFFFFu, splus, 0);
        const float L10 = __shfl_sync(0xFFFFFFFFu, sig,   1);
        const float L11 = __shfl_sync(0xFFFFFFFFu, splus, 2);
        const float L20 = __shfl_sync(0xFFFFFFFFu, sig,   3);
        const float L21 = __shfl_sync(0xFFFFFFFFu, sig,   4);
        const float L22 = __shfl_sync(0xFFFFFFFFu, splus, 5);

        if (lane == 0) {
            const float TWO_PI_1P5 = 15.749609945722419f;   // (2*pi)^1.5
            const float C = 1.0f / (L00 * L11 * L22 * TWO_PI_1P5);
            sp.qa[wid] = make_float4(dots[0] + bm[0], dots[1] + bm[1], dots[2] + bm[2],
                                     1.0f / L00);
            sp.qb[wid] = make_float4(L10, 1.0f / L11, L20, L21);
            sp.qc[wid] = make_float4(1.0f / L22, C, 0.0f, 0.0f);
        }
    }
    __syncthreads();

    // ---- streaming: 4 iterations; each = 2 consecutive slots (8 points, 96B in / 32B out)
    #pragma unroll
    for (int i = 0; i < NPAIR; i++) {
        const unsigned p0 = 4u * sPair;
        const unsigned r0 = rowof(p0);
        const unsigned rem = p0 - r0 * (unsigned)NPTS;
        const int i0 = (int)(r0 - r_first);

        const float4 qa = sp.qa[i0], qb = sp.qb[i0], qc = sp.qc[i0];

        float res[8];
        if (rem <= (unsigned)(NPTS - 8)) {
            // fast path (99.4%): all 8 points in row r0
            #pragma unroll
            for (int j = 0; j < 8; j++)
                res[j] = mvn_pt(f[3 * j + 0], f[3 * j + 1], f[3 * j + 2], qa, qb, qc);
        } else {
            // pair crosses the row boundary: points with rem+j >= NPTS use row r0+1
            const float4 qa2 = sp.qa[i0 + 1], qb2 = sp.qb[i0 + 1], qc2 = sp.qc[i0 + 1];
            #pragma unroll
            for (int j = 0; j < 8; j++) {
                const bool hi = (rem + (unsigned)j >= (unsigned)NPTS);
                res[j] = hi ? mvn_pt(f[3 * j + 0], f[3 * j + 1], f[3 * j + 2], qa2, qb2, qc2)
                            : mvn_pt(f[3 * j + 0], f[3 * j + 1], f[3 * j + 2], qa, qb, qc);
            }
        }

        stg256cs(out + (size_t)p0, res);

        if (i + 1 < NPAIR) {
            sPair += 2u * NTHR;
            const float* dp = dxyz + (size_t)sPair * 12u;
            ldg256cs(dp + 0,  f + 0);
            ldg256cs(dp + 8,  f + 8);
            ldg256cs(dp + 16, f + 16);
        }
    }
}

extern "C" void kernel_launch(void* const* d_in, const int* in_sizes, int n_in,
                              void* d_out, int out_size)
{
    const float* rep  = (const float*)d_in[0];
    const float* dxyz = (const float*)d_in[1];
    const float* Wm   = (const float*)d_in[2];
    const float* bm   = (const float*)d_in[3];
    const float* Ws   = (const float*)d_in[4];
    const float* bs   = (const float*)d_in[5];
    // d_in[6] = num_planes (fixed 3) — unused

    float* out = (float*)d_out;

    const int nrows = in_sizes[0] / DM;                       // 16384
    const unsigned total_slots = (unsigned)nrows * NPTS / 4u; // 5419008
    const unsigned blocks = total_slots / SPB;                // 2646, exact
    mvn_fused_kernel<<<blocks, NTHR>>>(rep, dxyz, Wm, bm, bs, Ws, out, nrows);
}

// round 13
// speedup vs baseline: 1.0367x; 1.0367x over previous
#include <cuda_runtime.h>

#define DM     64
#define NPTS   1323
#define NTHR   256
#define SPT    8                         // slots per thread
#define SPB    (NTHR * SPT)              // 2048 slots per block = 8192 points
#define NPAIR  (SPT / 2)                 // 4 pair-iterations
#define MAXR   8                         // rows a block can span

// exact p/1323 for p < ~2^31 (magic: ceil(2^40/1323) = 831074549)
__device__ __forceinline__ unsigned rowof(unsigned p) {
    return (unsigned)(((unsigned long long)p * 831074549ull) >> 40);
}

// one point through the inverse-Cholesky transform + gaussian
__device__ __forceinline__ float mvn_pt(float d0, float d1, float d2,
                                        float4 qa, float4 qb, float4 qc)
{
    d0 -= qa.x;
    d1 -= qa.y;
    d2 -= qa.z;
    float z0 = d0 * qa.w;
    float z1 = (d1 - qb.x * z0) * qb.y;
    float z2 = fmaf(-qb.w, z1, fmaf(-qb.z, z0, d2)) * qc.x;
    float maha = fmaf(z0, z0, fmaf(z1, z1, z2 * z2));
    return qc.y * __expf(-0.5f * maha);
}

struct SmemP { float4 qa[MAXR], qb[MAXR], qc[MAXR]; };

// one slot given staged data; params from block-local smem table
__device__ __forceinline__ float4 mvn_slot(unsigned s, unsigned r_first,
                                           float4 a, float4 b, float4 c,
                                           const SmemP* sp)
{
    const unsigned p0 = 4u * s;
    const unsigned r0 = rowof(p0);
    const unsigned r3 = rowof(p0 + 3u);
    const int i0 = (int)(r0 - r_first);

    const float4 qa = sp->qa[i0], qb = sp->qb[i0], qc = sp->qc[i0];

    float4 res;
    if (r0 == r3) {
        // fast path (99.7%)
        res.x = mvn_pt(a.x, a.y, a.z, qa, qb, qc);
        res.y = mvn_pt(a.w, b.x, b.y, qa, qb, qc);
        res.z = mvn_pt(b.z, b.w, c.x, qa, qb, qc);
        res.w = mvn_pt(c.y, c.z, c.w, qa, qb, qc);
    } else {
        // slot crosses a row boundary: points >= E use row r3's params
        const unsigned E = (r0 + 1u) * (unsigned)NPTS;
        const int i3 = (int)(r3 - r_first);
        const float4 qa2 = sp->qa[i3], qb2 = sp->qb[i3], qc2 = sp->qc[i3];
        res.x = (p0 + 0 < E) ? mvn_pt(a.x, a.y, a.z, qa, qb, qc)
                             : mvn_pt(a.x, a.y, a.z, qa2, qb2, qc2);
        res.y = (p0 + 1 < E) ? mvn_pt(a.w, b.x, b.y, qa, qb, qc)
                             : mvn_pt(a.w, b.x, b.y, qa2, qb2, qc2);
        res.z = (p0 + 2 < E) ? mvn_pt(b.z, b.w, c.x, qa, qb, qc)
                             : mvn_pt(b.z, b.w, c.x, qa2, qb2, qc2);
        res.w = (p0 + 3 < E) ? mvn_pt(c.y, c.z, c.w, qa, qb, qc)
                             : mvn_pt(c.y, c.z, c.w, qa2, qb2, qc2);
    }
    return res;
}

__global__ __launch_bounds__(NTHR, 5) void mvn_fused_kernel(
    const float* __restrict__ rep,
    const float* __restrict__ dxyz,
    const float* __restrict__ Wm,
    const float* __restrict__ bm,
    const float* __restrict__ bs_,
    const float* __restrict__ Ws,
    float* __restrict__ out,
    int nrows)
{
    __shared__ SmemP sp;

    const int t = threadIdx.x;
    const int wid = t >> 5, lane = t & 31;

    const unsigned sBase = blockIdx.x * (unsigned)SPB;
    const unsigned r_first = rowof(4u * sBase);

    const float4* __restrict__ dp4 = (const float4*)dxyz;

    // ---- issue the first PAIR's 6 loads before the prologue ----
    unsigned s0 = sBase + (unsigned)t;
    unsigned s1 = s0 + NTHR;
    float4 a0 = __ldcs(dp4 + 3u * (size_t)s0 + 0);
    float4 b0 = __ldcs(dp4 + 3u * (size_t)s0 + 1);
    float4 c0 = __ldcs(dp4 + 3u * (size_t)s0 + 2);
    float4 a1 = __ldcs(dp4 + 3u * (size_t)s1 + 0);
    float4 b1 = __ldcs(dp4 + 3u * (size_t)s1 + 1);
    float4 c1 = __ldcs(dp4 + 3u * (size_t)s1 + 2);

    // ---- prologue: warp w computes params for row r_first + w (all warps parallel) ----
    {
        int r = (int)r_first + wid;
        if (r > nrows - 1) r = nrows - 1;
        const float2 v = ((const float2*)(rep + (size_t)r * DM))[lane];

        float dots[9];
        #pragma unroll
        for (int cc = 0; cc < 9; cc++) {
            const float* w = (cc < 3) ? (Wm + cc * DM) : (Ws + (cc - 3) * DM);
            const float2 wv = ((const float2*)w)[lane];
            float partial = fmaf(v.x, wv.x, v.y * wv.y);
            #pragma unroll
            for (int off = 16; off > 0; off >>= 1)
                partial += __shfl_xor_sync(0xFFFFFFFFu, partial, off);
            dots[cc] = partial;   // full sum on every lane
        }

        float sig = 0.0f, splus = 0.0f;
        if (lane < 6) {
            sig = 1.0f / (1.0f + __expf(-(dots[3 + lane] + bs_[lane])));
            splus = __logf(1.0f + __expf(sig));   // sig in (0,1): always safe
        }
        const float L00 = __shfl_sync(0xFFFFFFFFu, splus, 0);
        const float L10 = __shfl_sync(0xFFFFFFFFu, sig,   1);
        const float L11 = __shfl_sync(0xFFFFFFFFu, splus, 2);
        const float L20 = __shfl_sync(0xFFFFFFFFu, sig,   3);
        const float L21 = __shfl_sync(0xFFFFFFFFu, sig,   4);
        const float L22 = __shfl_sync(0xFFFFFFFFu, splus, 5);

        if (lane == 0) {
            const float TWO_PI_1P5 = 15.749609945722419f;   // (2*pi)^1.5
            const float C = 1.0f / (L00 * L11 * L22 * TWO_PI_1P5);
            sp.qa[wid] = make_float4(dots[0] + bm[0], dots[1] + bm[1], dots[2] + bm[2],
                                     1.0f / L00);
            sp.qb[wid] = make_float4(L10, 1.0f / L11, L20, L21);
            sp.qc[wid] = make_float4(1.0f / L22, C, 0.0f, 0.0f);
        }
    }
    __syncthreads();

    // ---- streaming: 4 iterations x 2 slots; 6 loads issued back-to-back per pair ----
    #pragma unroll
    for (int i = 0; i < NPAIR; i++) {
        const float4 r0 = mvn_slot(s0, r_first, a0, b0, c0, &sp);
        const float4 r1 = mvn_slot(s1, r_first, a1, b1, c1, &sp);
        __stcs((float4*)out + s0, r0);
        __stcs((float4*)out + s1, r1);

        if (i + 1 < NPAIR) {
            s0 += 2u * NTHR;
            s1 += 2u * NTHR;
            a0 = __ldcs(dp4 + 3u * (size_t)s0 + 0);
            b0 = __ldcs(dp4 + 3u * (size_t)s0 + 1);
            c0 = __ldcs(dp4 + 3u * (size_t)s0 + 2);
            a1 = __ldcs(dp4 + 3u * (size_t)s1 + 0);
            b1 = __ldcs(dp4 + 3u * (size_t)s1 + 1);
            c1 = __ldcs(dp4 + 3u * (size_t)s1 + 2);
        }
    }
}

extern "C" void kernel_launch(void* const* d_in, const int* in_sizes, int n_in,
                              void* d_out, int out_size)
{
    const float* rep  = (const float*)d_in[0];
    const float* dxyz = (const float*)d_in[1];
    const float* Wm   = (const float*)d_in[2];
    const float* bm   = (const float*)d_in[3];
    const float* Ws   = (const float*)d_in[4];
    const float* bs   = (const float*)d_in[5];
    // d_in[6] = num_planes (fixed 3) — unused

    float* out = (float*)d_out;

    const int nrows = in_sizes[0] / DM;                       // 16384
    const unsigned total_slots = (unsigned)nrows * NPTS / 4u; // 5419008
    const unsigned blocks = total_slots / SPB;                // 2646, exact
    mvn_fused_kernel<<<blocks, NTHR>>>(rep, dxyz, Wm, bm, bs, Ws, out, nrows);
}